// round 12
// baseline (speedup 1.0000x reference)
#include <cuda_runtime.h>
#include <cstdio>

#define Bq 32
#define Tq 512
#define Iq 1024
#define Hq 1024
#define Gq 4096   // 4*H

// ---------------- scratch (device globals: no allocs allowed) ----------------
__device__ float g_gx[(size_t)Tq * Bq * Gq];   // 256 MB: gate pre-activations for current layer
__device__ float g_y0[(size_t)Tq * Bq * Hq];   // 64 MB: layer-0 outputs (time-major)
__device__ float g_part[4 * Bq * Gq];          // 2 MB: K-split partial sums of h @ W_hh^T
__device__ float g_h[2][Bq * Hq];
__device__ float g_c[2][Bq * Hq];

// software grid barrier state (self-resetting: bar_count returns to 0 each use)
__device__ unsigned g_bar_count = 0;
__device__ volatile unsigned g_bar_gen;      // monotonically increasing across uses/replays

// ---------------- init ----------------
__global__ void zero_state() {
    int idx = blockIdx.x * blockDim.x + threadIdx.x;
    if (idx < Bq * Hq) {
        g_h[0][idx] = 0.f; g_h[1][idx] = 0.f;
        g_c[0][idx] = 0.f; g_c[1][idx] = 0.f;
    }
}

// ---------------- grid barrier (all blocks co-resident by construction) -------------
__device__ __forceinline__ void grid_barrier(unsigned nblocks) {
    __syncthreads();
    if (threadIdx.x == 0) {
        __threadfence();                       // make this block's writes visible
        unsigned gen = g_bar_gen;
        unsigned ticket = atomicAdd(&g_bar_count, 1u);
        if (ticket == nblocks - 1u) {
            atomicExch(&g_bar_count, 0u);      // reset for next use
            __threadfence();
            g_bar_gen = gen + 1u;              // release (volatile store, L2)
        } else {
            while (g_bar_gen == gen) { }       // volatile spin on L2
        }
    }
    __syncthreads();
}

// ---------------- input projection GEMM ----------------
// C[M=T*B][4096] = A @ W^T + (b_ih + b_hh)
// A_elem(m,k) = A[(m/32)*t_stride + (m%32)*b_stride + k]
//   layer0: A=x [B,T,I]  -> t_stride=I,     b_stride=T*I
//   layer1: A=y0 [T,B,H] -> t_stride=B*H,   b_stride=H
__global__ __launch_bounds__(256) void gemm_gx(
    const float* __restrict__ A, int t_stride, int b_stride,
    const float* __restrict__ W,
    const float* __restrict__ b_ih, const float* __restrict__ b_hh,
    float* __restrict__ C)
{
    __shared__ float As[8][128];
    __shared__ float Bs[8][128];

    const int tid    = threadIdx.x;
    const int m_base = blockIdx.y * 128;
    const int n_base = blockIdx.x * 128;

    const int lm = tid >> 1;            // 0..127
    const int lk = (tid & 1) * 4;       // 0 or 4
    const int gm = m_base + lm;
    const float* Arow = A + (size_t)(gm >> 5) * t_stride + (size_t)(gm & 31) * b_stride + lk;
    const float* Wrow = W + (size_t)(n_base + lm) * Iq + lk;

    const int ty = tid >> 4;            // 0..15 -> rows ty*8..+7
    const int tx = tid & 15;            // 0..15 -> cols tx*8..+7

    float acc[8][8];
    #pragma unroll
    for (int i = 0; i < 8; i++)
        #pragma unroll
        for (int j = 0; j < 8; j++) acc[i][j] = 0.f;

    for (int k0 = 0; k0 < Iq; k0 += 8) {
        float4 av = *(const float4*)(Arow + k0);
        float4 wv = *(const float4*)(Wrow + k0);
        __syncthreads();
        As[lk + 0][lm] = av.x; As[lk + 1][lm] = av.y; As[lk + 2][lm] = av.z; As[lk + 3][lm] = av.w;
        Bs[lk + 0][lm] = wv.x; Bs[lk + 1][lm] = wv.y; Bs[lk + 2][lm] = wv.z; Bs[lk + 3][lm] = wv.w;
        __syncthreads();
        #pragma unroll
        for (int k = 0; k < 8; k++) {
            float a[8], b[8];
            *(float4*)&a[0] = *(const float4*)&As[k][ty * 8];
            *(float4*)&a[4] = *(const float4*)&As[k][ty * 8 + 4];
            *(float4*)&b[0] = *(const float4*)&Bs[k][tx * 8];
            *(float4*)&b[4] = *(const float4*)&Bs[k][tx * 8 + 4];
            #pragma unroll
            for (int i = 0; i < 8; i++)
                #pragma unroll
                for (int j = 0; j < 8; j++)
                    acc[i][j] += a[i] * b[j];
        }
    }

    #pragma unroll
    for (int j = 0; j < 8; j++) {
        int n = n_base + tx * 8 + j;
        float bias = b_ih[n] + b_hh[n];
        #pragma unroll
        for (int i = 0; i < 8; i++) acc[i][j] += bias;
    }
    #pragma unroll
    for (int i = 0; i < 8; i++) {
        float* Crow = C + (size_t)(m_base + ty * 8 + i) * Gq + n_base + tx * 8;
        *(float4*)(Crow)     = make_float4(acc[i][0], acc[i][1], acc[i][2], acc[i][3]);
        *(float4*)(Crow + 4) = make_float4(acc[i][4], acc[i][5], acc[i][6], acc[i][7]);
    }
}

// ---------------- persistent recurrent layer: 1 kernel = T steps ----------------
// grid = 128 blocks x 256 threads (co-resident on 148 SMs).
// Per step: phase A = K-split mm (block = 32 n-tiles x 4 k-splits, 4x4 micro-tile),
//           grid barrier, phase B = cell (exactly 1 element/thread), grid barrier.
__device__ __forceinline__ float sigmoidf_(float x) { return 1.f / (1.f + expf(-x)); }

__global__ __launch_bounds__(256) void lstm_layer_persist(
    const float* __restrict__ gx,   // [T, B, 4H]
    const float* __restrict__ W,    // [4H, H]
    float* __restrict__ h,          // [B, H]
    float* __restrict__ c,          // [B, H]
    float* __restrict__ y)          // [T, B, H]
{
    __shared__ float hs[32][36];    // [k][b]
    __shared__ float ws[32][132];   // [k][n]

    const unsigned nblocks = gridDim.x;
    const int tid    = threadIdx.x;
    const int n_base = (blockIdx.x & 31) * 128;
    const int k_base = (blockIdx.x >> 5) * 256;

    const int tm = tid >> 5;        // 0..7  -> batches tm*4..+3
    const int tn = tid & 31;        // 0..31 -> cols tn*4..+3

    const int lb  = tid >> 3;       // 0..31
    const int lk4 = (tid & 7) * 4;  // 0..28
    const int ln  = tid >> 1;       // 0..127
    const int lwk = (tid & 1) * 16; // 0 or 16

    const float* hp = h + (size_t)lb * Hq + k_base + lk4;
    const float* wp = W + (size_t)(n_base + ln) * Hq + k_base + lwk;
    float* pp = g_part + (size_t)(blockIdx.x >> 5) * (Bq * Gq) + n_base + tn * 4;

    // cell mapping: 128 blocks * 256 threads == Bq*Hq elements exactly
    const int cell_idx = blockIdx.x * 256 + tid;
    const int cb = cell_idx >> 10;
    const int cj = cell_idx & (Hq - 1);

    for (int t = 0; t < Tq; t++) {
        // ---------- phase A: part = h @ W^T (this block's k-chunk) ----------
        float acc[4][4] = {};
        for (int k0 = 0; k0 < 256; k0 += 32) {
            float4 hv = *(const float4*)(hp + k0);
            float4 w0 = *(const float4*)(wp + k0);
            float4 w1 = *(const float4*)(wp + k0 + 4);
            float4 w2 = *(const float4*)(wp + k0 + 8);
            float4 w3 = *(const float4*)(wp + k0 + 12);
            __syncthreads();
            hs[lk4 + 0][lb] = hv.x; hs[lk4 + 1][lb] = hv.y; hs[lk4 + 2][lb] = hv.z; hs[lk4 + 3][lb] = hv.w;
            ws[lwk + 0][ln] = w0.x; ws[lwk + 1][ln] = w0.y; ws[lwk + 2][ln] = w0.z; ws[lwk + 3][ln] = w0.w;
            ws[lwk + 4][ln] = w1.x; ws[lwk + 5][ln] = w1.y; ws[lwk + 6][ln] = w1.z; ws[lwk + 7][ln] = w1.w;
            ws[lwk + 8][ln] = w2.x; ws[lwk + 9][ln] = w2.y; ws[lwk +10][ln] = w2.z; ws[lwk +11][ln] = w2.w;
            ws[lwk +12][ln] = w3.x; ws[lwk +13][ln] = w3.y; ws[lwk +14][ln] = w3.z; ws[lwk +15][ln] = w3.w;
            __syncthreads();
            #pragma unroll
            for (int k = 0; k < 32; k++) {
                float4 a  = *(const float4*)&hs[k][tm * 4];
                float4 bq = *(const float4*)&ws[k][tn * 4];
                float av[4] = {a.x, a.y, a.z, a.w};
                float bv[4] = {bq.x, bq.y, bq.z, bq.w};
                #pragma unroll
                for (int i = 0; i < 4; i++)
                    #pragma unroll
                    for (int j = 0; j < 4; j++)
                        acc[i][j] += av[i] * bv[j];
            }
        }
        #pragma unroll
        for (int i = 0; i < 4; i++) {
            *(float4*)(pp + (size_t)(tm * 4 + i) * Gq) =
                make_float4(acc[i][0], acc[i][1], acc[i][2], acc[i][3]);
        }

        grid_barrier(nblocks);

        // ---------- phase B: cell update (1 element per thread) ----------
        {
            const float* gx_t = gx + (size_t)t * Bq * Gq;
            float g4[4];
            #pragma unroll
            for (int g = 0; g < 4; g++) {
                size_t col = (size_t)cb * Gq + g * Hq + cj;
                float v = gx_t[col];
                v += g_part[col];
                v += g_part[col + 1 * (size_t)Bq * Gq];
                v += g_part[col + 2 * (size_t)Bq * Gq];
                v += g_part[col + 3 * (size_t)Bq * Gq];
                g4[g] = v;
            }
            float ig = sigmoidf_(g4[0]);
            float fg = sigmoidf_(g4[1]);
            float gg = tanhf(g4[2]);
            float og = sigmoidf_(g4[3]);
            float cn = fg * c[cell_idx] + ig * gg;
            float hn = og * tanhf(cn);
            c[cell_idx] = cn;
            h[cell_idx] = hn;
            y[(size_t)t * Bq * Hq + cell_idx] = hn;
        }

        grid_barrier(nblocks);
    }
}

// ---------------- finals: h_stack [2,B,H], c_stack [2,B,H] after outputs ------------
__global__ void finalize(float* __restrict__ out) {
    int idx = blockIdx.x * blockDim.x + threadIdx.x;
    if (idx < Bq * Hq) {
        const size_t off = (size_t)Tq * Bq * Hq;
        out[off + 0 * (size_t)Bq * Hq + idx] = g_h[0][idx];
        out[off + 1 * (size_t)Bq * Hq + idx] = g_h[1][idx];
        out[off + 2 * (size_t)Bq * Hq + idx] = g_c[0][idx];
        out[off + 3 * (size_t)Bq * Hq + idx] = g_c[1][idx];
    }
}

// ---------------- launch ----------------
extern "C" void kernel_launch(void* const* d_in, const int* in_sizes, int n_in,
                              void* d_out, int out_size)
{
    const float* x     = (const float*)d_in[0];
    const float* W_ih0 = (const float*)d_in[1];
    const float* W_hh0 = (const float*)d_in[2];
    const float* b_ih0 = (const float*)d_in[3];
    const float* b_hh0 = (const float*)d_in[4];
    const float* W_ih1 = (const float*)d_in[5];
    const float* W_hh1 = (const float*)d_in[6];
    const float* b_ih1 = (const float*)d_in[7];
    const float* b_hh1 = (const float*)d_in[8];
    float* out = (float*)d_out;

    void *p_gx, *p_y0, *p_h, *p_c;
    cudaGetSymbolAddress(&p_gx, g_gx);
    cudaGetSymbolAddress(&p_y0, g_y0);
    cudaGetSymbolAddress(&p_h,  g_h);
    cudaGetSymbolAddress(&p_c,  g_c);
    float* gx = (float*)p_gx;
    float* y0 = (float*)p_y0;
    float* h0 = (float*)p_h;
    float* h1 = h0 + Bq * Hq;
    float* c0 = (float*)p_c;
    float* c1 = c0 + Bq * Hq;

    zero_state<<<128, 256>>>();

    // ---- layer 0 ----
    gemm_gx<<<dim3(32, 128), 256>>>(x, Iq, Tq * Iq, W_ih0, b_ih0, b_hh0, gx);
    lstm_layer_persist<<<128, 256>>>(gx, W_hh0, h0, c0, y0);

    // ---- layer 1 ----
    gemm_gx<<<dim3(32, 128), 256>>>(y0, Bq * Hq, Hq, W_ih1, b_ih1, b_hh1, gx);
    lstm_layer_persist<<<128, 256>>>(gx, W_hh1, h1, c1, out);

    finalize<<<128, 256>>>(out);
}

// round 13
// speedup vs baseline: 1.0011x; 1.0011x over previous
#include <cuda_runtime.h>
#include <cstdio>

#define Bq 32
#define Tq 512
#define Iq 1024
#define Hq 1024
#define Gq 4096   // 4*H

// ---------------- scratch (device globals: no allocs allowed) ----------------
__device__ float g_gx[(size_t)Tq * Bq * Gq];   // 256 MB: gate pre-activations for current layer
__device__ float g_y0[(size_t)Tq * Bq * Hq];   // 64 MB: layer-0 outputs (time-major)
__device__ float g_part[4 * Bq * Gq];          // 2 MB: K-split partial sums of h @ W_hh^T
__device__ float g_h[2][Bq * Hq];
__device__ float g_c[2][Bq * Hq];

// software grid barrier state (self-resetting: bar_count returns to 0 each use)
__device__ unsigned g_bar_count = 0;
__device__ volatile unsigned g_bar_gen;      // monotonically increasing across uses/replays

// ---------------- init ----------------
__global__ void zero_state() {
    int idx = blockIdx.x * blockDim.x + threadIdx.x;
    if (idx < Bq * Hq) {
        g_h[0][idx] = 0.f; g_h[1][idx] = 0.f;
        g_c[0][idx] = 0.f; g_c[1][idx] = 0.f;
    }
}

// ---------------- grid barrier (all blocks co-resident by construction) -------------
__device__ __forceinline__ void grid_barrier(unsigned nblocks) {
    __syncthreads();
    if (threadIdx.x == 0) {
        __threadfence();                       // make this block's writes visible
        unsigned gen = g_bar_gen;
        unsigned ticket = atomicAdd(&g_bar_count, 1u);
        if (ticket == nblocks - 1u) {
            atomicExch(&g_bar_count, 0u);      // reset for next use
            __threadfence();
            g_bar_gen = gen + 1u;              // release (volatile store, L2)
        } else {
            while (g_bar_gen == gen) { }       // volatile spin on L2
        }
    }
    __syncthreads();
}

// ---------------- input projection GEMM ----------------
// C[M=T*B][4096] = A @ W^T + (b_ih + b_hh)
// A_elem(m,k) = A[(m/32)*t_stride + (m%32)*b_stride + k]
//   layer0: A=x [B,T,I]  -> t_stride=I,     b_stride=T*I
//   layer1: A=y0 [T,B,H] -> t_stride=B*H,   b_stride=H
__global__ __launch_bounds__(256) void gemm_gx(
    const float* __restrict__ A, int t_stride, int b_stride,
    const float* __restrict__ W,
    const float* __restrict__ b_ih, const float* __restrict__ b_hh,
    float* __restrict__ C)
{
    __shared__ float As[8][128];
    __shared__ float Bs[8][128];

    const int tid    = threadIdx.x;
    const int m_base = blockIdx.y * 128;
    const int n_base = blockIdx.x * 128;

    const int lm = tid >> 1;            // 0..127
    const int lk = (tid & 1) * 4;       // 0 or 4
    const int gm = m_base + lm;
    const float* Arow = A + (size_t)(gm >> 5) * t_stride + (size_t)(gm & 31) * b_stride + lk;
    const float* Wrow = W + (size_t)(n_base + lm) * Iq + lk;

    const int ty = tid >> 4;            // 0..15 -> rows ty*8..+7
    const int tx = tid & 15;            // 0..15 -> cols tx*8..+7

    float acc[8][8];
    #pragma unroll
    for (int i = 0; i < 8; i++)
        #pragma unroll
        for (int j = 0; j < 8; j++) acc[i][j] = 0.f;

    for (int k0 = 0; k0 < Iq; k0 += 8) {
        float4 av = *(const float4*)(Arow + k0);
        float4 wv = *(const float4*)(Wrow + k0);
        __syncthreads();
        As[lk + 0][lm] = av.x; As[lk + 1][lm] = av.y; As[lk + 2][lm] = av.z; As[lk + 3][lm] = av.w;
        Bs[lk + 0][lm] = wv.x; Bs[lk + 1][lm] = wv.y; Bs[lk + 2][lm] = wv.z; Bs[lk + 3][lm] = wv.w;
        __syncthreads();
        #pragma unroll
        for (int k = 0; k < 8; k++) {
            float a[8], b[8];
            *(float4*)&a[0] = *(const float4*)&As[k][ty * 8];
            *(float4*)&a[4] = *(const float4*)&As[k][ty * 8 + 4];
            *(float4*)&b[0] = *(const float4*)&Bs[k][tx * 8];
            *(float4*)&b[4] = *(const float4*)&Bs[k][tx * 8 + 4];
            #pragma unroll
            for (int i = 0; i < 8; i++)
                #pragma unroll
                for (int j = 0; j < 8; j++)
                    acc[i][j] += a[i] * b[j];
        }
    }

    #pragma unroll
    for (int j = 0; j < 8; j++) {
        int n = n_base + tx * 8 + j;
        float bias = b_ih[n] + b_hh[n];
        #pragma unroll
        for (int i = 0; i < 8; i++) acc[i][j] += bias;
    }
    #pragma unroll
    for (int i = 0; i < 8; i++) {
        float* Crow = C + (size_t)(m_base + ty * 8 + i) * Gq + n_base + tx * 8;
        *(float4*)(Crow)     = make_float4(acc[i][0], acc[i][1], acc[i][2], acc[i][3]);
        *(float4*)(Crow + 4) = make_float4(acc[i][4], acc[i][5], acc[i][6], acc[i][7]);
    }
}

// ---------------- persistent recurrent layer: 1 kernel = T steps ----------------
// grid = 128 blocks x 256 threads (co-resident on 148 SMs).
// Per step: phase A = K-split mm (block = 32 n-tiles x 4 k-splits, 4x4 micro-tile),
//           grid barrier, phase B = cell (exactly 1 element/thread), grid barrier.
__device__ __forceinline__ float sigmoidf_(float x) { return 1.f / (1.f + expf(-x)); }

__global__ __launch_bounds__(256) void lstm_layer_persist(
    const float* __restrict__ gx,   // [T, B, 4H]
    const float* __restrict__ W,    // [4H, H]
    float* __restrict__ h,          // [B, H]
    float* __restrict__ c,          // [B, H]
    float* __restrict__ y)          // [T, B, H]
{
    __shared__ float hs[32][36];    // [k][b]
    __shared__ float ws[32][132];   // [k][n]

    const unsigned nblocks = gridDim.x;
    const int tid    = threadIdx.x;
    const int n_base = (blockIdx.x & 31) * 128;
    const int k_base = (blockIdx.x >> 5) * 256;

    const int tm = tid >> 5;        // 0..7  -> batches tm*4..+3
    const int tn = tid & 31;        // 0..31 -> cols tn*4..+3

    const int lb  = tid >> 3;       // 0..31
    const int lk4 = (tid & 7) * 4;  // 0..28
    const int ln  = tid >> 1;       // 0..127
    const int lwk = (tid & 1) * 16; // 0 or 16

    const float* hp = h + (size_t)lb * Hq + k_base + lk4;
    const float* wp = W + (size_t)(n_base + ln) * Hq + k_base + lwk;
    float* pp = g_part + (size_t)(blockIdx.x >> 5) * (Bq * Gq) + n_base + tn * 4;

    // cell mapping: 128 blocks * 256 threads == Bq*Hq elements exactly
    const int cell_idx = blockIdx.x * 256 + tid;
    const int cb = cell_idx >> 10;
    const int cj = cell_idx & (Hq - 1);

    for (int t = 0; t < Tq; t++) {
        // ---------- phase A: part = h @ W^T (this block's k-chunk) ----------
        float acc[4][4] = {};
        for (int k0 = 0; k0 < 256; k0 += 32) {
            float4 hv = *(const float4*)(hp + k0);
            float4 w0 = *(const float4*)(wp + k0);
            float4 w1 = *(const float4*)(wp + k0 + 4);
            float4 w2 = *(const float4*)(wp + k0 + 8);
            float4 w3 = *(const float4*)(wp + k0 + 12);
            __syncthreads();
            hs[lk4 + 0][lb] = hv.x; hs[lk4 + 1][lb] = hv.y; hs[lk4 + 2][lb] = hv.z; hs[lk4 + 3][lb] = hv.w;
            ws[lwk + 0][ln] = w0.x; ws[lwk + 1][ln] = w0.y; ws[lwk + 2][ln] = w0.z; ws[lwk + 3][ln] = w0.w;
            ws[lwk + 4][ln] = w1.x; ws[lwk + 5][ln] = w1.y; ws[lwk + 6][ln] = w1.z; ws[lwk + 7][ln] = w1.w;
            ws[lwk + 8][ln] = w2.x; ws[lwk + 9][ln] = w2.y; ws[lwk +10][ln] = w2.z; ws[lwk +11][ln] = w2.w;
            ws[lwk +12][ln] = w3.x; ws[lwk +13][ln] = w3.y; ws[lwk +14][ln] = w3.z; ws[lwk +15][ln] = w3.w;
            __syncthreads();
            #pragma unroll
            for (int k = 0; k < 32; k++) {
                float4 a  = *(const float4*)&hs[k][tm * 4];
                float4 bq = *(const float4*)&ws[k][tn * 4];
                float av[4] = {a.x, a.y, a.z, a.w};
                float bv[4] = {bq.x, bq.y, bq.z, bq.w};
                #pragma unroll
                for (int i = 0; i < 4; i++)
                    #pragma unroll
                    for (int j = 0; j < 4; j++)
                        acc[i][j] += av[i] * bv[j];
            }
        }
        #pragma unroll
        for (int i = 0; i < 4; i++) {
            *(float4*)(pp + (size_t)(tm * 4 + i) * Gq) =
                make_float4(acc[i][0], acc[i][1], acc[i][2], acc[i][3]);
        }

        grid_barrier(nblocks);

        // ---------- phase B: cell update (1 element per thread) ----------
        {
            const float* gx_t = gx + (size_t)t * Bq * Gq;
            float g4[4];
            #pragma unroll
            for (int g = 0; g < 4; g++) {
                size_t col = (size_t)cb * Gq + g * Hq + cj;
                float v = gx_t[col];
                v += g_part[col];
                v += g_part[col + 1 * (size_t)Bq * Gq];
                v += g_part[col + 2 * (size_t)Bq * Gq];
                v += g_part[col + 3 * (size_t)Bq * Gq];
                g4[g] = v;
            }
            float ig = sigmoidf_(g4[0]);
            float fg = sigmoidf_(g4[1]);
            float gg = tanhf(g4[2]);
            float og = sigmoidf_(g4[3]);
            float cn = fg * c[cell_idx] + ig * gg;
            float hn = og * tanhf(cn);
            c[cell_idx] = cn;
            h[cell_idx] = hn;
            y[(size_t)t * Bq * Hq + cell_idx] = hn;
        }

        grid_barrier(nblocks);
    }
}

// ---------------- finals: h_stack [2,B,H], c_stack [2,B,H] after outputs ------------
__global__ void finalize(float* __restrict__ out) {
    int idx = blockIdx.x * blockDim.x + threadIdx.x;
    if (idx < Bq * Hq) {
        const size_t off = (size_t)Tq * Bq * Hq;
        out[off + 0 * (size_t)Bq * Hq + idx] = g_h[0][idx];
        out[off + 1 * (size_t)Bq * Hq + idx] = g_h[1][idx];
        out[off + 2 * (size_t)Bq * Hq + idx] = g_c[0][idx];
        out[off + 3 * (size_t)Bq * Hq + idx] = g_c[1][idx];
    }
}

// ---------------- launch ----------------
extern "C" void kernel_launch(void* const* d_in, const int* in_sizes, int n_in,
                              void* d_out, int out_size)
{
    const float* x     = (const float*)d_in[0];
    const float* W_ih0 = (const float*)d_in[1];
    const float* W_hh0 = (const float*)d_in[2];
    const float* b_ih0 = (const float*)d_in[3];
    const float* b_hh0 = (const float*)d_in[4];
    const float* W_ih1 = (const float*)d_in[5];
    const float* W_hh1 = (const float*)d_in[6];
    const float* b_ih1 = (const float*)d_in[7];
    const float* b_hh1 = (const float*)d_in[8];
    float* out = (float*)d_out;

    void *p_gx, *p_y0, *p_h, *p_c;
    cudaGetSymbolAddress(&p_gx, g_gx);
    cudaGetSymbolAddress(&p_y0, g_y0);
    cudaGetSymbolAddress(&p_h,  g_h);
    cudaGetSymbolAddress(&p_c,  g_c);
    float* gx = (float*)p_gx;
    float* y0 = (float*)p_y0;
    float* h0 = (float*)p_h;
    float* h1 = h0 + Bq * Hq;
    float* c0 = (float*)p_c;
    float* c1 = c0 + Bq * Hq;

    zero_state<<<128, 256>>>();

    // ---- layer 0 ----
    gemm_gx<<<dim3(32, 128), 256>>>(x, Iq, Tq * Iq, W_ih0, b_ih0, b_hh0, gx);
    lstm_layer_persist<<<128, 256>>>(gx, W_hh0, h0, c0, y0);

    // ---- layer 1 ----
    gemm_gx<<<dim3(32, 128), 256>>>(y0, Bq * Hq, Hq, W_ih1, b_ih1, b_hh1, gx);
    lstm_layer_persist<<<128, 256>>>(gx, W_hh1, h1, c1, out);

    finalize<<<128, 256>>>(out);
}

// round 14
// speedup vs baseline: 1.0040x; 1.0029x over previous
#include <cuda_runtime.h>
#include <cstdio>

#define Bq 32
#define Tq 512
#define Iq 1024
#define Hq 1024
#define Gq 4096   // 4*H

// ---------------- scratch (device globals: no allocs allowed) ----------------
__device__ float g_gx[(size_t)Tq * Bq * Gq];   // 256 MB: gate pre-activations for current layer
__device__ float g_y0[(size_t)Tq * Bq * Hq];   // 64 MB: layer-0 outputs (time-major)
__device__ float g_part[4 * Bq * Gq];          // 2 MB: K-split partial sums of h @ W_hh^T
__device__ float g_h[2][Bq * Hq];
__device__ float g_c[2][Bq * Hq];

// software grid barrier state (self-resetting: bar_count returns to 0 each use)
__device__ unsigned g_bar_count = 0;
__device__ volatile unsigned g_bar_gen;      // monotonically increasing across uses/replays

// ---------------- init ----------------
__global__ void zero_state() {
    int idx = blockIdx.x * blockDim.x + threadIdx.x;
    if (idx < Bq * Hq) {
        g_h[0][idx] = 0.f; g_h[1][idx] = 0.f;
        g_c[0][idx] = 0.f; g_c[1][idx] = 0.f;
    }
}

// ---------------- grid barrier (all blocks co-resident by construction) -------------
__device__ __forceinline__ void grid_barrier(unsigned nblocks) {
    __syncthreads();
    if (threadIdx.x == 0) {
        __threadfence();                       // make this block's writes visible
        unsigned gen = g_bar_gen;
        unsigned ticket = atomicAdd(&g_bar_count, 1u);
        if (ticket == nblocks - 1u) {
            atomicExch(&g_bar_count, 0u);      // reset for next use
            __threadfence();
            g_bar_gen = gen + 1u;              // release (volatile store, L2)
        } else {
            while (g_bar_gen == gen) { }       // volatile spin on L2
        }
    }
    __syncthreads();
}

// ---------------- input projection GEMM ----------------
// C[M=T*B][4096] = A @ W^T + (b_ih + b_hh)
// A_elem(m,k) = A[(m/32)*t_stride + (m%32)*b_stride + k]
//   layer0: A=x [B,T,I]  -> t_stride=I,     b_stride=T*I
//   layer1: A=y0 [T,B,H] -> t_stride=B*H,   b_stride=H
__global__ __launch_bounds__(256) void gemm_gx(
    const float* __restrict__ A, int t_stride, int b_stride,
    const float* __restrict__ W,
    const float* __restrict__ b_ih, const float* __restrict__ b_hh,
    float* __restrict__ C)
{
    __shared__ float As[8][128];
    __shared__ float Bs[8][128];

    const int tid    = threadIdx.x;
    const int m_base = blockIdx.y * 128;
    const int n_base = blockIdx.x * 128;

    const int lm = tid >> 1;            // 0..127
    const int lk = (tid & 1) * 4;       // 0 or 4
    const int gm = m_base + lm;
    const float* Arow = A + (size_t)(gm >> 5) * t_stride + (size_t)(gm & 31) * b_stride + lk;
    const float* Wrow = W + (size_t)(n_base + lm) * Iq + lk;

    const int ty = tid >> 4;            // 0..15 -> rows ty*8..+7
    const int tx = tid & 15;            // 0..15 -> cols tx*8..+7

    float acc[8][8];
    #pragma unroll
    for (int i = 0; i < 8; i++)
        #pragma unroll
        for (int j = 0; j < 8; j++) acc[i][j] = 0.f;

    for (int k0 = 0; k0 < Iq; k0 += 8) {
        float4 av = *(const float4*)(Arow + k0);
        float4 wv = *(const float4*)(Wrow + k0);
        __syncthreads();
        As[lk + 0][lm] = av.x; As[lk + 1][lm] = av.y; As[lk + 2][lm] = av.z; As[lk + 3][lm] = av.w;
        Bs[lk + 0][lm] = wv.x; Bs[lk + 1][lm] = wv.y; Bs[lk + 2][lm] = wv.z; Bs[lk + 3][lm] = wv.w;
        __syncthreads();
        #pragma unroll
        for (int k = 0; k < 8; k++) {
            float a[8], b[8];
            *(float4*)&a[0] = *(const float4*)&As[k][ty * 8];
            *(float4*)&a[4] = *(const float4*)&As[k][ty * 8 + 4];
            *(float4*)&b[0] = *(const float4*)&Bs[k][tx * 8];
            *(float4*)&b[4] = *(const float4*)&Bs[k][tx * 8 + 4];
            #pragma unroll
            for (int i = 0; i < 8; i++)
                #pragma unroll
                for (int j = 0; j < 8; j++)
                    acc[i][j] += a[i] * b[j];
        }
    }

    #pragma unroll
    for (int j = 0; j < 8; j++) {
        int n = n_base + tx * 8 + j;
        float bias = b_ih[n] + b_hh[n];
        #pragma unroll
        for (int i = 0; i < 8; i++) acc[i][j] += bias;
    }
    #pragma unroll
    for (int i = 0; i < 8; i++) {
        float* Crow = C + (size_t)(m_base + ty * 8 + i) * Gq + n_base + tx * 8;
        *(float4*)(Crow)     = make_float4(acc[i][0], acc[i][1], acc[i][2], acc[i][3]);
        *(float4*)(Crow + 4) = make_float4(acc[i][4], acc[i][5], acc[i][6], acc[i][7]);
    }
}

// ---------------- persistent recurrent layer: 1 kernel = T steps ----------------
// grid = 128 blocks x 256 threads (co-resident on 148 SMs).
// Per step: phase A = K-split mm (block = 32 n-tiles x 4 k-splits, 4x4 micro-tile),
//           grid barrier, phase B = cell (exactly 1 element/thread), grid barrier.
__device__ __forceinline__ float sigmoidf_(float x) { return 1.f / (1.f + expf(-x)); }

__global__ __launch_bounds__(256) void lstm_layer_persist(
    const float* __restrict__ gx,   // [T, B, 4H]
    const float* __restrict__ W,    // [4H, H]
    float* __restrict__ h,          // [B, H]
    float* __restrict__ c,          // [B, H]
    float* __restrict__ y)          // [T, B, H]
{
    __shared__ float hs[32][36];    // [k][b]
    __shared__ float ws[32][132];   // [k][n]

    const unsigned nblocks = gridDim.x;
    const int tid    = threadIdx.x;
    const int n_base = (blockIdx.x & 31) * 128;
    const int k_base = (blockIdx.x >> 5) * 256;

    const int tm = tid >> 5;        // 0..7  -> batches tm*4..+3
    const int tn = tid & 31;        // 0..31 -> cols tn*4..+3

    const int lb  = tid >> 3;       // 0..31
    const int lk4 = (tid & 7) * 4;  // 0..28
    const int ln  = tid >> 1;       // 0..127
    const int lwk = (tid & 1) * 16; // 0 or 16

    const float* hp = h + (size_t)lb * Hq + k_base + lk4;
    const float* wp = W + (size_t)(n_base + ln) * Hq + k_base + lwk;
    float* pp = g_part + (size_t)(blockIdx.x >> 5) * (Bq * Gq) + n_base + tn * 4;

    // cell mapping: 128 blocks * 256 threads == Bq*Hq elements exactly
    const int cell_idx = blockIdx.x * 256 + tid;
    const int cb = cell_idx >> 10;
    const int cj = cell_idx & (Hq - 1);

    for (int t = 0; t < Tq; t++) {
        // ---------- phase A: part = h @ W^T (this block's k-chunk) ----------
        float acc[4][4] = {};
        for (int k0 = 0; k0 < 256; k0 += 32) {
            float4 hv = *(const float4*)(hp + k0);
            float4 w0 = *(const float4*)(wp + k0);
            float4 w1 = *(const float4*)(wp + k0 + 4);
            float4 w2 = *(const float4*)(wp + k0 + 8);
            float4 w3 = *(const float4*)(wp + k0 + 12);
            __syncthreads();
            hs[lk4 + 0][lb] = hv.x; hs[lk4 + 1][lb] = hv.y; hs[lk4 + 2][lb] = hv.z; hs[lk4 + 3][lb] = hv.w;
            ws[lwk + 0][ln] = w0.x; ws[lwk + 1][ln] = w0.y; ws[lwk + 2][ln] = w0.z; ws[lwk + 3][ln] = w0.w;
            ws[lwk + 4][ln] = w1.x; ws[lwk + 5][ln] = w1.y; ws[lwk + 6][ln] = w1.z; ws[lwk + 7][ln] = w1.w;
            ws[lwk + 8][ln] = w2.x; ws[lwk + 9][ln] = w2.y; ws[lwk +10][ln] = w2.z; ws[lwk +11][ln] = w2.w;
            ws[lwk +12][ln] = w3.x; ws[lwk +13][ln] = w3.y; ws[lwk +14][ln] = w3.z; ws[lwk +15][ln] = w3.w;
            __syncthreads();
            #pragma unroll
            for (int k = 0; k < 32; k++) {
                float4 a  = *(const float4*)&hs[k][tm * 4];
                float4 bq = *(const float4*)&ws[k][tn * 4];
                float av[4] = {a.x, a.y, a.z, a.w};
                float bv[4] = {bq.x, bq.y, bq.z, bq.w};
                #pragma unroll
                for (int i = 0; i < 4; i++)
                    #pragma unroll
                    for (int j = 0; j < 4; j++)
                        acc[i][j] += av[i] * bv[j];
            }
        }
        #pragma unroll
        for (int i = 0; i < 4; i++) {
            *(float4*)(pp + (size_t)(tm * 4 + i) * Gq) =
                make_float4(acc[i][0], acc[i][1], acc[i][2], acc[i][3]);
        }

        grid_barrier(nblocks);

        // ---------- phase B: cell update (1 element per thread) ----------
        {
            const float* gx_t = gx + (size_t)t * Bq * Gq;
            float g4[4];
            #pragma unroll
            for (int g = 0; g < 4; g++) {
                size_t col = (size_t)cb * Gq + g * Hq + cj;
                float v = gx_t[col];
                v += g_part[col];
                v += g_part[col + 1 * (size_t)Bq * Gq];
                v += g_part[col + 2 * (size_t)Bq * Gq];
                v += g_part[col + 3 * (size_t)Bq * Gq];
                g4[g] = v;
            }
            float ig = sigmoidf_(g4[0]);
            float fg = sigmoidf_(g4[1]);
            float gg = tanhf(g4[2]);
            float og = sigmoidf_(g4[3]);
            float cn = fg * c[cell_idx] + ig * gg;
            float hn = og * tanhf(cn);
            c[cell_idx] = cn;
            h[cell_idx] = hn;
            y[(size_t)t * Bq * Hq + cell_idx] = hn;
        }

        grid_barrier(nblocks);
    }
}

// ---------------- finals: h_stack [2,B,H], c_stack [2,B,H] after outputs ------------
__global__ void finalize(float* __restrict__ out) {
    int idx = blockIdx.x * blockDim.x + threadIdx.x;
    if (idx < Bq * Hq) {
        const size_t off = (size_t)Tq * Bq * Hq;
        out[off + 0 * (size_t)Bq * Hq + idx] = g_h[0][idx];
        out[off + 1 * (size_t)Bq * Hq + idx] = g_h[1][idx];
        out[off + 2 * (size_t)Bq * Hq + idx] = g_c[0][idx];
        out[off + 3 * (size_t)Bq * Hq + idx] = g_c[1][idx];
    }
}

// ---------------- launch ----------------
extern "C" void kernel_launch(void* const* d_in, const int* in_sizes, int n_in,
                              void* d_out, int out_size)
{
    const float* x     = (const float*)d_in[0];
    const float* W_ih0 = (const float*)d_in[1];
    const float* W_hh0 = (const float*)d_in[2];
    const float* b_ih0 = (const float*)d_in[3];
    const float* b_hh0 = (const float*)d_in[4];
    const float* W_ih1 = (const float*)d_in[5];
    const float* W_hh1 = (const float*)d_in[6];
    const float* b_ih1 = (const float*)d_in[7];
    const float* b_hh1 = (const float*)d_in[8];
    float* out = (float*)d_out;

    void *p_gx, *p_y0, *p_h, *p_c;
    cudaGetSymbolAddress(&p_gx, g_gx);
    cudaGetSymbolAddress(&p_y0, g_y0);
    cudaGetSymbolAddress(&p_h,  g_h);
    cudaGetSymbolAddress(&p_c,  g_c);
    float* gx = (float*)p_gx;
    float* y0 = (float*)p_y0;
    float* h0 = (float*)p_h;
    float* h1 = h0 + Bq * Hq;
    float* c0 = (float*)p_c;
    float* c1 = c0 + Bq * Hq;

    zero_state<<<128, 256>>>();

    // ---- layer 0 ----
    gemm_gx<<<dim3(32, 128), 256>>>(x, Iq, Tq * Iq, W_ih0, b_ih0, b_hh0, gx);
    lstm_layer_persist<<<128, 256>>>(gx, W_hh0, h0, c0, y0);

    // ---- layer 1 ----
    gemm_gx<<<dim3(32, 128), 256>>>(y0, Bq * Hq, Hq, W_ih1, b_ih1, b_hh1, gx);
    lstm_layer_persist<<<128, 256>>>(gx, W_hh1, h1, c1, out);

    finalize<<<128, 256>>>(out);
}